// round 5
// baseline (speedup 1.0000x reference)
#include <cuda_runtime.h>
#include <cstdint>

// Problem constants
#define NSEG 6
#define NCH  512
#define NPOS 16384     // 128*128
#define NBINS 16

// ---------------- device scratch (no allocation allowed) ----------------
__device__ unsigned g_mbits[NSEG * 512];     // bit-packed mask, 512 u32/segment
__device__ int      g_posA[NSEG * NBINS];    // bin window start (position)
__device__ int      g_posB[NSEG * NBINS];    // bin window end (exclusive)
__device__ float    g_rdenom[NSEG * NBINS];  // 1/denom per bin
__device__ float    g_ys[NSEG * NCH * NBINS];
__device__ float    g_h1p[4][NSEG * 2048];   // fcA partials (K-split 4)
__device__ float    g_h2p[2][NSEG * 512];    // fcB partials (K-split 2)
__device__ float    g_w0[NSEG * 512];

// ---------------- K1: mask + scan + bin boundaries ----------------
__global__ void __launch_bounds__(512) k_prep(const int* __restrict__ parsing)
{
    const int s = blockIdx.x;
    const int tid = threadIdx.x;
    __shared__ int ssum[512];
    __shared__ int sstart[NBINS], send[NBINS];

    const int4* __restrict__ pv = (const int4*)(parsing + s * 65536); // [256,256]
    const int base = tid * 32;   // 32 consecutive positions, same h row

    int cnt = 0;
    unsigned mw = 0;
    const int h = base >> 7;
    const int w0 = base & 127;
#pragma unroll
    for (int j = 0; j < 32; j += 2) {
        int w = w0 + j;
        int4 v = pv[h * 128 + (w >> 1)];
        int m0 = (v.x != 0);
        int m1 = (v.z != 0);
        cnt += m0 + m1;
        mw |= ((unsigned)m0) << j;
        mw |= ((unsigned)m1) << (j + 1);
    }
    g_mbits[s * 512 + tid] = mw;

    ssum[tid] = cnt;
    __syncthreads();
    for (int off = 1; off < 512; off <<= 1) {
        int v = (tid >= off) ? ssum[tid - off] : 0;
        __syncthreads();
        ssum[tid] += v;
        __syncthreads();
    }
    const int incl = ssum[tid];
    const int L    = ssum[511];
    const int exc  = incl - cnt;

    if (tid < NBINS) {
        int k  = tid;
        int st = (k * L) >> 4;
        int en = ((k + 1) * L + 15) >> 4;
        sstart[k] = st;
        send[k]   = en;
        int d = en - st; if (d < 1) d = 1;
        g_rdenom[s * NBINS + k] = 1.0f / (float)d;
        g_posA[s * NBINS + k] = 0;
        g_posB[s * NBINS + k] = 0;
    }
    __syncthreads();

    int r = exc;
#pragma unroll 1
    for (int j = 0; j < 32; j++) {
        if ((mw >> j) & 1u) {
            int p = base + j;
            for (int k = 0; k < NBINS; k++) {
                if (r == sstart[k])     g_posA[s * NBINS + k] = p;
                if (r + 1 == send[k])   g_posB[s * NBINS + k] = p + 1;
            }
            r++;
        }
    }
}

// ---------------- K2: masked adaptive pool (unroll 4) ----------------
__global__ void __launch_bounds__(512) k_pool(const float* __restrict__ xs)
{
    const int sc   = blockIdx.x;          // s*512 + c
    const int s    = sc >> 9;
    const int warp = threadIdx.x >> 5;
    const int lane = threadIdx.x & 31;

    const int lo = g_posA[s * NBINS + warp];
    const int hi = g_posB[s * NBINS + warp];

    const float4* __restrict__ x4 = (const float4*)(xs + ((size_t)sc << 14));
    const unsigned* __restrict__ mb = g_mbits + s * 512;

    float a0 = 0.f, a1 = 0.f;
    const int i1 = (hi + 3) >> 2;
    int i = (lo >> 2) + lane;
    for (; i + 96 < i1; i += 128) {
        float4 v0 = x4[i];
        float4 v1 = x4[i + 32];
        float4 v2 = x4[i + 64];
        float4 v3 = x4[i + 96];
        unsigned n0 = mb[i >> 3] >> ((i & 7) << 2);
        unsigned n1 = mb[(i + 32) >> 3] >> (((i + 32) & 7) << 2);
        unsigned n2 = mb[(i + 64) >> 3] >> (((i + 64) & 7) << 2);
        unsigned n3 = mb[(i + 96) >> 3] >> (((i + 96) & 7) << 2);
        int p0 = i << 2, p1 = (i + 32) << 2, p2 = (i + 64) << 2, p3 = (i + 96) << 2;
        a0 += ((n0 & 1u) && p0     >= lo && p0     < hi) ? v0.x : 0.f;
        a1 += ((n0 & 2u) && p0 + 1 >= lo && p0 + 1 < hi) ? v0.y : 0.f;
        a0 += ((n0 & 4u) && p0 + 2 >= lo && p0 + 2 < hi) ? v0.z : 0.f;
        a1 += ((n0 & 8u) && p0 + 3 >= lo && p0 + 3 < hi) ? v0.w : 0.f;
        a0 += ((n1 & 1u) && p1     >= lo && p1     < hi) ? v1.x : 0.f;
        a1 += ((n1 & 2u) && p1 + 1 >= lo && p1 + 1 < hi) ? v1.y : 0.f;
        a0 += ((n1 & 4u) && p1 + 2 >= lo && p1 + 2 < hi) ? v1.z : 0.f;
        a1 += ((n1 & 8u) && p1 + 3 >= lo && p1 + 3 < hi) ? v1.w : 0.f;
        a0 += ((n2 & 1u) && p2     >= lo && p2     < hi) ? v2.x : 0.f;
        a1 += ((n2 & 2u) && p2 + 1 >= lo && p2 + 1 < hi) ? v2.y : 0.f;
        a0 += ((n2 & 4u) && p2 + 2 >= lo && p2 + 2 < hi) ? v2.z : 0.f;
        a1 += ((n2 & 8u) && p2 + 3 >= lo && p2 + 3 < hi) ? v2.w : 0.f;
        a0 += ((n3 & 1u) && p3     >= lo && p3     < hi) ? v3.x : 0.f;
        a1 += ((n3 & 2u) && p3 + 1 >= lo && p3 + 1 < hi) ? v3.y : 0.f;
        a0 += ((n3 & 4u) && p3 + 2 >= lo && p3 + 2 < hi) ? v3.z : 0.f;
        a1 += ((n3 & 8u) && p3 + 3 >= lo && p3 + 3 < hi) ? v3.w : 0.f;
    }
    for (; i < i1; i += 32) {
        float4 v = x4[i];
        unsigned nib = mb[i >> 3] >> ((i & 7) << 2);
        int pb = i << 2;
        a0 += ((nib & 1u) && pb     >= lo && pb     < hi) ? v.x : 0.f;
        a1 += ((nib & 2u) && pb + 1 >= lo && pb + 1 < hi) ? v.y : 0.f;
        a0 += ((nib & 4u) && pb + 2 >= lo && pb + 2 < hi) ? v.z : 0.f;
        a1 += ((nib & 8u) && pb + 3 >= lo && pb + 3 < hi) ? v.w : 0.f;
    }
    float acc = a0 + a1;
#pragma unroll
    for (int o = 16; o; o >>= 1) acc += __shfl_xor_sync(0xffffffffu, acc, o);
    if (lane == 0) {
        int c = sc & 511;
        g_ys[s * (NCH * NBINS) + c * NBINS + warp] = acc * g_rdenom[s * NBINS + warp];
    }
}

// ---------------- helpers ----------------
__device__ __forceinline__ float dot4(float4 a, float4 b, float acc)
{
    acc = fmaf(a.x, b.x, acc);
    acc = fmaf(a.y, b.y, acc);
    acc = fmaf(a.z, b.z, acc);
    acc = fmaf(a.w, b.w, acc);
    return acc;
}
__device__ __forceinline__ float4 add4(float4 a, float4 b)
{ return make_float4(a.x + b.x, a.y + b.y, a.z + b.z, a.w + b.w); }

__device__ __forceinline__ float warp_red(float a)
{
#pragma unroll
    for (int o = 16; o; o >>= 1) a += __shfl_xor_sync(0xffffffffu, a, o);
    return a;
}

__global__ void k_noop() {}

// ---------------- fcA: 2048x8192 GEMV, K-split 4 ----------------
// grid = 6 * 256 * 4 = 6144 blocks, 256 threads (8 rows/block).
__global__ void __launch_bounds__(256) k_fcA(const float* __restrict__ W)
{
    __shared__ float4 sx[512];                // 2048-float chunk of ys
    const int bid   = blockIdx.x;
    const int s     = bid >> 10;              // / 1024
    const int rem   = bid & 1023;
    const int chunk = rem >> 8;               // / 256
    const int row   = (rem & 255) * 8 + (threadIdx.x >> 5);
    const int lane  = threadIdx.x & 31;

    const float4* __restrict__ xv = (const float4*)(g_ys + s * 8192 + chunk * 2048);
    for (int i = threadIdx.x; i < 512; i += 256) sx[i] = xv[i];
    __syncthreads();

    const float4* __restrict__ wv =
        (const float4*)(W + (size_t)(s * 2048 + row) * 8192 + chunk * 2048);

    float a0 = 0.f, a1 = 0.f, a2 = 0.f, a3 = 0.f;
#pragma unroll 1
    for (int t = 0; t < 4; t++) {
        const int b = t * 128 + lane;
        float4 w0 = wv[b], w1 = wv[b + 32], w2 = wv[b + 64], w3 = wv[b + 96];
        a0 = dot4(w0, sx[b], a0);
        a1 = dot4(w1, sx[b + 32], a1);
        a2 = dot4(w2, sx[b + 64], a2);
        a3 = dot4(w3, sx[b + 96], a3);
    }
    float a = warp_red((a0 + a1) + (a2 + a3));
    if (lane == 0) g_h1p[chunk][s * 2048 + row] = a;
}

// ---------------- fcB: 512x2048 GEMV, K-split 2; x = sum(fcA partials)+bA ----
// grid = 6 * 64 * 2 = 768 blocks.
__global__ void __launch_bounds__(256) k_fcB(const float* __restrict__ W,
                                             const float* __restrict__ bA)
{
    __shared__ float4 sx[256];                // 1024-float chunk of h1
    const int bid   = blockIdx.x;
    const int s     = bid >> 7;               // / 128
    const int rem   = bid & 127;
    const int chunk = rem >> 6;
    const int row   = (rem & 63) * 8 + (threadIdx.x >> 5);
    const int lane  = threadIdx.x & 31;

    const int xoff = (s * 2048 + chunk * 1024) >> 2;   // float4 offset
    {
        const float4* p0 = ((const float4*)g_h1p[0]) + xoff;
        const float4* p1 = ((const float4*)g_h1p[1]) + xoff;
        const float4* p2 = ((const float4*)g_h1p[2]) + xoff;
        const float4* p3 = ((const float4*)g_h1p[3]) + xoff;
        const float4* bb = ((const float4*)bA) + ((s * 2048 + chunk * 1024) >> 2);
        for (int i = threadIdx.x; i < 256; i += 256)
            sx[i] = add4(add4(add4(p0[i], p1[i]), add4(p2[i], p3[i])), bb[i]);
    }
    __syncthreads();

    const float4* __restrict__ wv =
        (const float4*)(W + (size_t)(s * 512 + row) * 2048 + chunk * 1024);

    float a0 = 0.f, a1 = 0.f, a2 = 0.f, a3 = 0.f;
#pragma unroll 1
    for (int t = 0; t < 2; t++) {
        const int b = t * 128 + lane;
        float4 w0 = wv[b], w1 = wv[b + 32], w2 = wv[b + 64], w3 = wv[b + 96];
        a0 = dot4(w0, sx[b], a0);
        a1 = dot4(w1, sx[b + 32], a1);
        a2 = dot4(w2, sx[b + 64], a2);
        a3 = dot4(w3, sx[b + 96], a3);
    }
    float a = warp_red((a0 + a1) + (a2 + a3));
    if (lane == 0) g_h2p[chunk][s * 512 + row] = a;
}

// ---------------- fcC: 512x512 GEMV; x = sum(fcB partials)+bB -------------
// grid = 6 * 64 = 384 blocks.
__global__ void __launch_bounds__(256) k_fcC(const float* __restrict__ W,
                                             const float* __restrict__ bB,
                                             const float* __restrict__ bC,
                                             float* __restrict__ out)
{
    __shared__ float4 sx[128];                // 512 floats of h2
    const int bid  = blockIdx.x;
    const int s    = bid >> 6;
    const int row  = (bid & 63) * 8 + (threadIdx.x >> 5);
    const int lane = threadIdx.x & 31;

    {
        const int xoff = (s * 512) >> 2;
        const float4* p0 = ((const float4*)g_h2p[0]) + xoff;
        const float4* p1 = ((const float4*)g_h2p[1]) + xoff;
        const float4* bb = ((const float4*)bB) + xoff;
        if (threadIdx.x < 128)
            sx[threadIdx.x] = add4(add4(p0[threadIdx.x], p1[threadIdx.x]), bb[threadIdx.x]);
    }
    __syncthreads();

    const float4* __restrict__ wv = (const float4*)(W + (size_t)(s * 512 + row) * 512);

    const int b = lane;
    float a0 = dot4(wv[b],      sx[b],      0.f);
    float a1 = dot4(wv[b + 32], sx[b + 32], 0.f);
    float a2 = dot4(wv[b + 64], sx[b + 64], 0.f);
    float a3 = dot4(wv[b + 96], sx[b + 96], 0.f);
    float a = warp_red((a0 + a1) + (a2 + a3));
    if (lane == 0) {
        float r = a + bC[s * 512 + row];
        g_w0[s * 512 + row] = r;
        out[s * 960 + row]  = r;
    }
}

// ---------------- tail: p1 -> p2 -> p3 fused, 6 blocks ----------------
__device__ __forceinline__ void tail_layer(const float* __restrict__ W,
                                           const float* __restrict__ bias,
                                           const float* __restrict__ xsm,
                                           float* __restrict__ ysm,
                                           float* __restrict__ out, int rows, int klen,
                                           int wid, int lane)
{
    const int k4 = klen >> 2;
    for (int row = wid; row < rows; row += 8) {
        const float4* wr = (const float4*)(W + (size_t)row * klen);
        const float4* xr = (const float4*)xsm;
        float a = 0.f;
        for (int i = lane; i < k4; i += 32) a = dot4(wr[i], xr[i], a);
        a = warp_red(a);
        if (lane == 0) {
            float r = a + bias[row];
            if (ysm) ysm[row] = r;
            out[row] = r;
        }
    }
}

__global__ void __launch_bounds__(256) k_tail(
    const float* __restrict__ p1w, const float* __restrict__ p1b,
    const float* __restrict__ p2w, const float* __restrict__ p2b,
    const float* __restrict__ p3w, const float* __restrict__ p3b,
    float* __restrict__ out)
{
    const int s = blockIdx.x;
    const int wid = threadIdx.x >> 5;
    const int lane = threadIdx.x & 31;
    __shared__ float sw0[512], sw1[256], sw2[128];

    for (int i = threadIdx.x; i < 512; i += 256) sw0[i] = g_w0[s * 512 + i];
    __syncthreads();
    tail_layer(p1w, p1b, sw0, sw1, out + s * 960 + 512, 256, 512, wid, lane);
    __syncthreads();
    tail_layer(p2w, p2b, sw1, sw2, out + s * 960 + 768, 128, 256, wid, lane);
    __syncthreads();
    tail_layer(p3w, p3b, sw2, nullptr, out + s * 960 + 896, 64, 128, wid, lane);
}

// ---------------- launch ----------------
extern "C" void kernel_launch(void* const* d_in, const int* in_sizes, int n_in,
                              void* d_out, int out_size)
{
    const float* xs      = (const float*)d_in[0];
    const int*   parsing = (const int*)  d_in[1];
    const float* fcA_w   = (const float*)d_in[2];
    const float* fcA_b   = (const float*)d_in[3];
    const float* fcB_w   = (const float*)d_in[4];
    const float* fcB_b   = (const float*)d_in[5];
    const float* fcC_w   = (const float*)d_in[6];
    const float* fcC_b   = (const float*)d_in[7];
    const float* p1_w    = (const float*)d_in[8];
    const float* p1_b    = (const float*)d_in[9];
    const float* p2_w    = (const float*)d_in[10];
    const float* p2_b    = (const float*)d_in[11];
    const float* p3_w    = (const float*)d_in[12];
    const float* p3_b    = (const float*)d_in[13];
    float* out = (float*)d_out;

    k_prep<<<NSEG, 512>>>(parsing);          // #0
    k_pool<<<NSEG * NCH, 512>>>(xs);         // #1
    k_noop<<<1, 32>>>();                     // #2 (slot filler so fcA is launch #3 -> profiled)
    k_fcA <<<NSEG * 256 * 4, 256>>>(fcA_w);  // #3
    k_fcB <<<NSEG * 64 * 2, 256>>>(fcB_w, fcA_b);
    k_fcC <<<NSEG * 64, 256>>>(fcC_w, fcB_b, fcC_b, out);
    k_tail<<<NSEG, 256>>>(p1_w, p1_b, p2_w, p2_b, p3_w, p3_b, out);
}

// round 6
// speedup vs baseline: 1.7098x; 1.7098x over previous
#include <cuda_runtime.h>
#include <cstdint>

// Problem constants
#define NSEG 6
#define NCH  512
#define NPOS 16384     // 128*128
#define NBINS 16

// ---------------- device scratch (no allocation allowed) ----------------
__device__ unsigned g_mbits[NSEG * 512];     // bit-packed mask, 512 u32/segment
__device__ float    g_fm[NSEG * NPOS];       // float 0/1 mask per position
__device__ int      g_posA[NSEG * NBINS];    // bin window start (position)
__device__ int      g_posB[NSEG * NBINS];    // bin window end (exclusive)
__device__ float    g_rdenom[NSEG * NBINS];  // 1/denom per bin
__device__ float    g_ys[NSEG * NCH * NBINS];
__device__ float    g_h1p[4][NSEG * 2048];   // fcA partials (K-split 4)
__device__ float    g_h2p[2][NSEG * 512];    // fcB partials (K-split 2)
__device__ float    g_w0[NSEG * 512];

// ---------------- K1: mask + scan + bin boundaries + float mask ----------
__global__ void __launch_bounds__(512) k_prep(const int* __restrict__ parsing)
{
    const int s = blockIdx.x;
    const int tid = threadIdx.x;
    __shared__ int ssum[512];
    __shared__ int sstart[NBINS], send[NBINS];

    const int4* __restrict__ pv = (const int4*)(parsing + s * 65536); // [256,256]
    const int base = tid * 32;   // 32 consecutive positions, same h row

    int cnt = 0;
    unsigned mw = 0;
    const int h = base >> 7;
    const int w0 = base & 127;
#pragma unroll
    for (int j = 0; j < 32; j += 2) {
        int w = w0 + j;
        int4 v = pv[h * 128 + (w >> 1)];
        int m0 = (v.x != 0);
        int m1 = (v.z != 0);
        cnt += m0 + m1;
        mw |= ((unsigned)m0) << j;
        mw |= ((unsigned)m1) << (j + 1);
    }
    g_mbits[s * 512 + tid] = mw;

    // float 0/1 mask, 8 float4 stores (128B contiguous per thread)
    {
        float4* fmv = (float4*)(g_fm + s * NPOS + base);
#pragma unroll
        for (int q = 0; q < 8; q++) {
            float4 f;
            f.x = ((mw >> (4 * q))     & 1u) ? 1.f : 0.f;
            f.y = ((mw >> (4 * q + 1)) & 1u) ? 1.f : 0.f;
            f.z = ((mw >> (4 * q + 2)) & 1u) ? 1.f : 0.f;
            f.w = ((mw >> (4 * q + 3)) & 1u) ? 1.f : 0.f;
            fmv[q] = f;
        }
    }

    ssum[tid] = cnt;
    __syncthreads();
    for (int off = 1; off < 512; off <<= 1) {
        int v = (tid >= off) ? ssum[tid - off] : 0;
        __syncthreads();
        ssum[tid] += v;
        __syncthreads();
    }
    const int incl = ssum[tid];
    const int L    = ssum[511];
    const int exc  = incl - cnt;

    if (tid < NBINS) {
        int k  = tid;
        int st = (k * L) >> 4;
        int en = ((k + 1) * L + 15) >> 4;
        sstart[k] = st;
        send[k]   = en;
        int d = en - st; if (d < 1) d = 1;
        g_rdenom[s * NBINS + k] = 1.0f / (float)d;
        g_posA[s * NBINS + k] = 0;
        g_posB[s * NBINS + k] = 0;
    }
    __syncthreads();

    int r = exc;
#pragma unroll 1
    for (int j = 0; j < 32; j++) {
        if ((mw >> j) & 1u) {
            int p = base + j;
            for (int k = 0; k < NBINS; k++) {
                if (r == sstart[k])     g_posA[s * NBINS + k] = p;
                if (r + 1 == send[k])   g_posB[s * NBINS + k] = p + 1;
            }
            r++;
        }
    }
}

// ---------------- packed f32x2 FMA ----------------
__device__ __forceinline__ void ffma2(unsigned long long& acc,
                                      unsigned long long v,
                                      unsigned long long m)
{
    asm("fma.rn.f32x2 %0, %1, %2, %0;" : "+l"(acc) : "l"(v), "l"(m));
}

// ---------------- K2: masked adaptive pool (fm-weighted FFMA2) ----------
// grid = NSEG*NCH blocks, 512 threads = 16 warps; warp k owns bin k.
__global__ void __launch_bounds__(512) k_pool(const float* __restrict__ xs)
{
    const int sc   = blockIdx.x;          // s*512 + c
    const int s    = sc >> 9;
    const int warp = threadIdx.x >> 5;
    const int lane = threadIdx.x & 31;

    const int lo = g_posA[s * NBINS + warp];
    const int hi = g_posB[s * NBINS + warp];

    const float4* __restrict__ x4  = (const float4*)(xs + ((size_t)sc << 14));
    const float4* __restrict__ fm4 = (const float4*)(g_fm + s * NPOS);

    // interior float4 range: every element of float4 i is inside [lo,hi)
    const int ilo2 = (lo + 3) >> 2;       // ceil(lo/4)
    const int ihi2 = hi >> 2;             // floor(hi/4)

    unsigned long long acc2 = 0;          // packed {0.f, 0.f}
    float accE = 0.f;

    int i = ilo2 + lane;
    for (; i + 32 < ihi2; i += 64) {
        float4 v0 = x4[i];
        float4 f0 = fm4[i];
        float4 v1 = x4[i + 32];
        float4 f1 = fm4[i + 32];
        ffma2(acc2, *(const unsigned long long*)&v0.x, *(const unsigned long long*)&f0.x);
        ffma2(acc2, *(const unsigned long long*)&v0.z, *(const unsigned long long*)&f0.z);
        ffma2(acc2, *(const unsigned long long*)&v1.x, *(const unsigned long long*)&f1.x);
        ffma2(acc2, *(const unsigned long long*)&v1.z, *(const unsigned long long*)&f1.z);
    }
    if (i < ihi2) {
        float4 v0 = x4[i];
        float4 f0 = fm4[i];
        ffma2(acc2, *(const unsigned long long*)&v0.x, *(const unsigned long long*)&f0.x);
        ffma2(acc2, *(const unsigned long long*)&v0.z, *(const unsigned long long*)&f0.z);
    }

    // edge float4s (at most 1 on each side), with explicit window checks
    if (lane == 0) {
        for (int e = (lo >> 2); e < ilo2; e++) {
            float4 v = x4[e];
            float4 f = fm4[e];
            int p = e << 2;
            accE += (p     >= lo && p     < hi) ? v.x * f.x : 0.f;
            accE += (p + 1 >= lo && p + 1 < hi) ? v.y * f.y : 0.f;
            accE += (p + 2 >= lo && p + 2 < hi) ? v.z * f.z : 0.f;
            accE += (p + 3 >= lo && p + 3 < hi) ? v.w * f.w : 0.f;
        }
    }
    if (lane == 1) {
        int e0 = (ihi2 > ilo2) ? ihi2 : ilo2;
        for (int e = e0; e < ((hi + 3) >> 2); e++) {
            float4 v = x4[e];
            float4 f = fm4[e];
            int p = e << 2;
            accE += (p     >= lo && p     < hi) ? v.x * f.x : 0.f;
            accE += (p + 1 >= lo && p + 1 < hi) ? v.y * f.y : 0.f;
            accE += (p + 2 >= lo && p + 2 < hi) ? v.z * f.z : 0.f;
            accE += (p + 3 >= lo && p + 3 < hi) ? v.w * f.w : 0.f;
        }
    }

    float2 a2 = *(float2*)&acc2;
    float acc = a2.x + a2.y + accE;
#pragma unroll
    for (int o = 16; o; o >>= 1) acc += __shfl_xor_sync(0xffffffffu, acc, o);
    if (lane == 0) {
        int c = sc & 511;
        g_ys[s * (NCH * NBINS) + c * NBINS + warp] = acc * g_rdenom[s * NBINS + warp];
    }
}

// ---------------- helpers ----------------
__device__ __forceinline__ float dot4(float4 a, float4 b, float acc)
{
    acc = fmaf(a.x, b.x, acc);
    acc = fmaf(a.y, b.y, acc);
    acc = fmaf(a.z, b.z, acc);
    acc = fmaf(a.w, b.w, acc);
    return acc;
}
__device__ __forceinline__ float4 add4(float4 a, float4 b)
{ return make_float4(a.x + b.x, a.y + b.y, a.z + b.z, a.w + b.w); }

__device__ __forceinline__ float warp_red(float a)
{
#pragma unroll
    for (int o = 16; o; o >>= 1) a += __shfl_xor_sync(0xffffffffu, a, o);
    return a;
}

__global__ void k_noop() {}

// ---------------- fcA: 2048x8192 GEMV, K-split 4 ----------------
// grid = 6 * 256 * 4 = 6144 blocks, 256 threads (8 rows/block).
__global__ void __launch_bounds__(256) k_fcA(const float* __restrict__ W)
{
    __shared__ float4 sx[512];                // 2048-float chunk of ys
    const int bid   = blockIdx.x;
    const int s     = bid >> 10;              // / 1024
    const int rem   = bid & 1023;
    const int chunk = rem >> 8;               // / 256
    const int row   = (rem & 255) * 8 + (threadIdx.x >> 5);
    const int lane  = threadIdx.x & 31;

    const float4* __restrict__ xv = (const float4*)(g_ys + s * 8192 + chunk * 2048);
    for (int i = threadIdx.x; i < 512; i += 256) sx[i] = xv[i];
    __syncthreads();

    const float4* __restrict__ wv =
        (const float4*)(W + (size_t)(s * 2048 + row) * 8192 + chunk * 2048);

    float a0 = 0.f, a1 = 0.f, a2 = 0.f, a3 = 0.f;
#pragma unroll 1
    for (int t = 0; t < 4; t++) {
        const int b = t * 128 + lane;
        float4 w0 = wv[b], w1 = wv[b + 32], w2 = wv[b + 64], w3 = wv[b + 96];
        a0 = dot4(w0, sx[b], a0);
        a1 = dot4(w1, sx[b + 32], a1);
        a2 = dot4(w2, sx[b + 64], a2);
        a3 = dot4(w3, sx[b + 96], a3);
    }
    float a = warp_red((a0 + a1) + (a2 + a3));
    if (lane == 0) g_h1p[chunk][s * 2048 + row] = a;
}

// ---------------- fcB: 512x2048 GEMV, K-split 2; x = sum(fcA partials)+bA ----
__global__ void __launch_bounds__(256) k_fcB(const float* __restrict__ W,
                                             const float* __restrict__ bA)
{
    __shared__ float4 sx[256];                // 1024-float chunk of h1
    const int bid   = blockIdx.x;
    const int s     = bid >> 7;               // / 128
    const int rem   = bid & 127;
    const int chunk = rem >> 6;
    const int row   = (rem & 63) * 8 + (threadIdx.x >> 5);
    const int lane  = threadIdx.x & 31;

    const int xoff = (s * 2048 + chunk * 1024) >> 2;   // float4 offset
    {
        const float4* p0 = ((const float4*)g_h1p[0]) + xoff;
        const float4* p1 = ((const float4*)g_h1p[1]) + xoff;
        const float4* p2 = ((const float4*)g_h1p[2]) + xoff;
        const float4* p3 = ((const float4*)g_h1p[3]) + xoff;
        const float4* bb = ((const float4*)bA) + xoff;
        for (int i = threadIdx.x; i < 256; i += 256)
            sx[i] = add4(add4(add4(p0[i], p1[i]), add4(p2[i], p3[i])), bb[i]);
    }
    __syncthreads();

    const float4* __restrict__ wv =
        (const float4*)(W + (size_t)(s * 512 + row) * 2048 + chunk * 1024);

    float a0 = 0.f, a1 = 0.f, a2 = 0.f, a3 = 0.f;
#pragma unroll 1
    for (int t = 0; t < 2; t++) {
        const int b = t * 128 + lane;
        float4 w0 = wv[b], w1 = wv[b + 32], w2 = wv[b + 64], w3 = wv[b + 96];
        a0 = dot4(w0, sx[b], a0);
        a1 = dot4(w1, sx[b + 32], a1);
        a2 = dot4(w2, sx[b + 64], a2);
        a3 = dot4(w3, sx[b + 96], a3);
    }
    float a = warp_red((a0 + a1) + (a2 + a3));
    if (lane == 0) g_h2p[chunk][s * 512 + row] = a;
}

// ---------------- fcC: 512x512 GEMV; x = sum(fcB partials)+bB -------------
__global__ void __launch_bounds__(256) k_fcC(const float* __restrict__ W,
                                             const float* __restrict__ bB,
                                             const float* __restrict__ bC,
                                             float* __restrict__ out)
{
    __shared__ float4 sx[128];                // 512 floats of h2
    const int bid  = blockIdx.x;
    const int s    = bid >> 6;
    const int row  = (bid & 63) * 8 + (threadIdx.x >> 5);
    const int lane = threadIdx.x & 31;

    {
        const int xoff = (s * 512) >> 2;
        const float4* p0 = ((const float4*)g_h2p[0]) + xoff;
        const float4* p1 = ((const float4*)g_h2p[1]) + xoff;
        const float4* bb = ((const float4*)bB) + xoff;
        if (threadIdx.x < 128)
            sx[threadIdx.x] = add4(add4(p0[threadIdx.x], p1[threadIdx.x]), bb[threadIdx.x]);
    }
    __syncthreads();

    const float4* __restrict__ wv = (const float4*)(W + (size_t)(s * 512 + row) * 512);

    const int b = lane;
    float a0 = dot4(wv[b],      sx[b],      0.f);
    float a1 = dot4(wv[b + 32], sx[b + 32], 0.f);
    float a2 = dot4(wv[b + 64], sx[b + 64], 0.f);
    float a3 = dot4(wv[b + 96], sx[b + 96], 0.f);
    float a = warp_red((a0 + a1) + (a2 + a3));
    if (lane == 0) {
        float r = a + bC[s * 512 + row];
        g_w0[s * 512 + row] = r;
        out[s * 960 + row]  = r;
    }
}

// ---------------- tail: p1 -> p2 -> p3 fused, 6 blocks x 1024 thr ---------
__device__ __forceinline__ void tail_layer(const float* __restrict__ W,
                                           const float* __restrict__ bias,
                                           const float* __restrict__ xsm,
                                           float* __restrict__ ysm,
                                           float* __restrict__ out, int rows, int klen,
                                           int wid, int lane)
{
    const int k4 = klen >> 2;
    for (int row = wid; row < rows; row += 32) {
        const float4* wr = (const float4*)(W + (size_t)row * klen);
        const float4* xr = (const float4*)xsm;
        float a = 0.f;
        for (int i = lane; i < k4; i += 32) a = dot4(wr[i], xr[i], a);
        a = warp_red(a);
        if (lane == 0) {
            float r = a + bias[row];
            if (ysm) ysm[row] = r;
            out[row] = r;
        }
    }
}

__global__ void __launch_bounds__(1024) k_tail(
    const float* __restrict__ p1w, const float* __restrict__ p1b,
    const float* __restrict__ p2w, const float* __restrict__ p2b,
    const float* __restrict__ p3w, const float* __restrict__ p3b,
    float* __restrict__ out)
{
    const int s = blockIdx.x;
    const int wid = threadIdx.x >> 5;
    const int lane = threadIdx.x & 31;
    __shared__ float sw0[512], sw1[256], sw2[128];

    if (threadIdx.x < 512) sw0[threadIdx.x] = g_w0[s * 512 + threadIdx.x];
    __syncthreads();
    tail_layer(p1w, p1b, sw0, sw1, out + s * 960 + 512, 256, 512, wid, lane);
    __syncthreads();
    tail_layer(p2w, p2b, sw1, sw2, out + s * 960 + 768, 128, 256, wid, lane);
    __syncthreads();
    tail_layer(p3w, p3b, sw2, nullptr, out + s * 960 + 896, 64, 128, wid, lane);
}

// ---------------- launch ----------------
extern "C" void kernel_launch(void* const* d_in, const int* in_sizes, int n_in,
                              void* d_out, int out_size)
{
    const float* xs      = (const float*)d_in[0];
    const int*   parsing = (const int*)  d_in[1];
    const float* fcA_w   = (const float*)d_in[2];
    const float* fcA_b   = (const float*)d_in[3];
    const float* fcB_w   = (const float*)d_in[4];
    const float* fcB_b   = (const float*)d_in[5];
    const float* fcC_w   = (const float*)d_in[6];
    const float* fcC_b   = (const float*)d_in[7];
    const float* p1_w    = (const float*)d_in[8];
    const float* p1_b    = (const float*)d_in[9];
    const float* p2_w    = (const float*)d_in[10];
    const float* p2_b    = (const float*)d_in[11];
    const float* p3_w    = (const float*)d_in[12];
    const float* p3_b    = (const float*)d_in[13];
    float* out = (float*)d_out;

    k_prep<<<NSEG, 512>>>(parsing);          // #0
    k_noop<<<1, 32>>>();                     // #1
    k_noop<<<1, 32>>>();                     // #2
    k_pool<<<NSEG * NCH, 512>>>(xs);         // #3  <- profiled launch
    k_fcA <<<NSEG * 256 * 4, 256>>>(fcA_w);
    k_fcB <<<NSEG * 64 * 2, 256>>>(fcB_w, fcA_b);
    k_fcC <<<NSEG * 64, 256>>>(fcC_w, fcB_b, fcC_b, out);
    k_tail<<<NSEG, 1024>>>(p1_w, p1_b, p2_w, p2_b, p3_w, p3_b, out);
}

// round 7
// speedup vs baseline: 1.7647x; 1.0321x over previous
#include <cuda_runtime.h>
#include <cstdint>

// Problem constants
#define NSEG 6
#define NCH  512
#define NPOS 16384     // 128*128
#define NBINS 16

// ---------------- device scratch (no allocation allowed) ----------------
__device__ unsigned g_mbits[NSEG * 512];     // bit-packed mask, 512 u32/segment
__device__ float    g_fm[NSEG * NPOS];       // float 0/1 mask per position
__device__ int      g_posA[NSEG * NBINS];    // bin window start (position)
__device__ int      g_posB[NSEG * NBINS];    // bin window end (exclusive)
__device__ float    g_rdenom[NSEG * NBINS];  // 1/denom per bin
__device__ float    g_ys[NSEG * NCH * NBINS];
__device__ float    g_h1p[4][NSEG * 2048];   // fcA partials (K-split 4)
__device__ float    g_h2p[2][NSEG * 512];    // fcB partials (K-split 2)
__device__ float    g_w0[NSEG * 512];

// ---------------- K1: mask + scan + bin boundaries + float mask ----------
__global__ void __launch_bounds__(512) k_prep(const int* __restrict__ parsing)
{
    const int s = blockIdx.x;
    const int tid = threadIdx.x;
    __shared__ int ssum[512];
    __shared__ int sstart[NBINS], send[NBINS];

    const int4* __restrict__ pv = (const int4*)(parsing + s * 65536); // [256,256]
    const int base = tid * 32;   // 32 consecutive positions, same h row

    int cnt = 0;
    unsigned mw = 0;
    const int h = base >> 7;
    const int w0 = base & 127;
#pragma unroll
    for (int j = 0; j < 32; j += 2) {
        int w = w0 + j;
        int4 v = pv[h * 128 + (w >> 1)];
        int m0 = (v.x != 0);
        int m1 = (v.z != 0);
        cnt += m0 + m1;
        mw |= ((unsigned)m0) << j;
        mw |= ((unsigned)m1) << (j + 1);
    }
    g_mbits[s * 512 + tid] = mw;

    // float 0/1 mask, 8 float4 stores (128B contiguous per thread)
    {
        float4* fmv = (float4*)(g_fm + s * NPOS + base);
#pragma unroll
        for (int q = 0; q < 8; q++) {
            float4 f;
            f.x = ((mw >> (4 * q))     & 1u) ? 1.f : 0.f;
            f.y = ((mw >> (4 * q + 1)) & 1u) ? 1.f : 0.f;
            f.z = ((mw >> (4 * q + 2)) & 1u) ? 1.f : 0.f;
            f.w = ((mw >> (4 * q + 3)) & 1u) ? 1.f : 0.f;
            fmv[q] = f;
        }
    }

    ssum[tid] = cnt;
    __syncthreads();
    for (int off = 1; off < 512; off <<= 1) {
        int v = (tid >= off) ? ssum[tid - off] : 0;
        __syncthreads();
        ssum[tid] += v;
        __syncthreads();
    }
    const int incl = ssum[tid];
    const int L    = ssum[511];
    const int exc  = incl - cnt;

    if (tid < NBINS) {
        int k  = tid;
        int st = (k * L) >> 4;
        int en = ((k + 1) * L + 15) >> 4;
        sstart[k] = st;
        send[k]   = en;
        int d = en - st; if (d < 1) d = 1;
        g_rdenom[s * NBINS + k] = 1.0f / (float)d;
        g_posA[s * NBINS + k] = 0;
        g_posB[s * NBINS + k] = 0;
    }
    __syncthreads();

    int r = exc;
#pragma unroll 1
    for (int j = 0; j < 32; j++) {
        if ((mw >> j) & 1u) {
            int p = base + j;
            for (int k = 0; k < NBINS; k++) {
                if (r == sstart[k])     g_posA[s * NBINS + k] = p;
                if (r + 1 == send[k])   g_posB[s * NBINS + k] = p + 1;
            }
            r++;
        }
    }
}

// ---------------- packed f32x2 FMA ----------------
__device__ __forceinline__ void ffma2(unsigned long long& acc,
                                      unsigned long long v,
                                      unsigned long long m)
{
    asm("fma.rn.f32x2 %0, %1, %2, %0;" : "+l"(acc) : "l"(v), "l"(m));
}
#define ULL(f4part) (*(const unsigned long long*)&(f4part))

// ---------------- K2: masked adaptive pool, 2 channels / warp ------------
// grid = NSEG * 256 blocks (channel pairs), 512 threads = 16 warps (bin each).
__global__ void __launch_bounds__(512, 2) k_pool(const float* __restrict__ xs)
{
    const int bid  = blockIdx.x;          // s*256 + cp
    const int s    = bid >> 8;
    const int cp   = bid & 255;
    const int c0   = cp * 2;
    const int warp = threadIdx.x >> 5;
    const int lane = threadIdx.x & 31;

    const int lo = g_posA[s * NBINS + warp];
    const int hi = g_posB[s * NBINS + warp];

    const size_t chbase = ((size_t)(s * NCH + c0)) << 14;
    const float4* __restrict__ xa4 = (const float4*)(xs + chbase);
    const float4* __restrict__ xb4 = xa4 + (NPOS >> 2);
    const float4* __restrict__ fm4 = (const float4*)(g_fm + s * NPOS);

    const int ilo2 = (lo + 3) >> 2;       // first fully-inside float4
    const int ihi2 = hi >> 2;             // end of fully-inside float4s

    unsigned long long accA = 0, accB = 0;
    float eA = 0.f, eB = 0.f;

    int i = ilo2 + lane;
    for (; i + 32 < ihi2; i += 64) {
        float4 f0 = fm4[i];
        float4 a0 = xa4[i];
        float4 b0 = xb4[i];
        float4 f1 = fm4[i + 32];
        float4 a1 = xa4[i + 32];
        float4 b1 = xb4[i + 32];
        ffma2(accA, ULL(a0.x), ULL(f0.x));
        ffma2(accA, ULL(a0.z), ULL(f0.z));
        ffma2(accB, ULL(b0.x), ULL(f0.x));
        ffma2(accB, ULL(b0.z), ULL(f0.z));
        ffma2(accA, ULL(a1.x), ULL(f1.x));
        ffma2(accA, ULL(a1.z), ULL(f1.z));
        ffma2(accB, ULL(b1.x), ULL(f1.x));
        ffma2(accB, ULL(b1.z), ULL(f1.z));
    }
    if (i < ihi2) {
        float4 f0 = fm4[i];
        float4 a0 = xa4[i];
        float4 b0 = xb4[i];
        ffma2(accA, ULL(a0.x), ULL(f0.x));
        ffma2(accA, ULL(a0.z), ULL(f0.z));
        ffma2(accB, ULL(b0.x), ULL(f0.x));
        ffma2(accB, ULL(b0.z), ULL(f0.z));
    }

    // edge float4s (≤1 each side) with explicit window checks
    if (lane == 0) {
        for (int e = (lo >> 2); e < ilo2; e++) {
            float4 fa = fm4[e];
            float4 va = xa4[e];
            float4 vb = xb4[e];
            int p = e << 2;
            float m0 = (p     >= lo && p     < hi) ? fa.x : 0.f;
            float m1 = (p + 1 >= lo && p + 1 < hi) ? fa.y : 0.f;
            float m2 = (p + 2 >= lo && p + 2 < hi) ? fa.z : 0.f;
            float m3 = (p + 3 >= lo && p + 3 < hi) ? fa.w : 0.f;
            eA += va.x * m0 + va.y * m1 + va.z * m2 + va.w * m3;
            eB += vb.x * m0 + vb.y * m1 + vb.z * m2 + vb.w * m3;
        }
    }
    if (lane == 1) {
        int e0 = (ihi2 > ilo2) ? ihi2 : ilo2;
        for (int e = e0; e < ((hi + 3) >> 2); e++) {
            float4 fa = fm4[e];
            float4 va = xa4[e];
            float4 vb = xb4[e];
            int p = e << 2;
            float m0 = (p     >= lo && p     < hi) ? fa.x : 0.f;
            float m1 = (p + 1 >= lo && p + 1 < hi) ? fa.y : 0.f;
            float m2 = (p + 2 >= lo && p + 2 < hi) ? fa.z : 0.f;
            float m3 = (p + 3 >= lo && p + 3 < hi) ? fa.w : 0.f;
            eA += va.x * m0 + va.y * m1 + va.z * m2 + va.w * m3;
            eB += vb.x * m0 + vb.y * m1 + vb.z * m2 + vb.w * m3;
        }
    }

    float2 a2 = *(float2*)&accA;
    float2 b2 = *(float2*)&accB;
    float accAf = a2.x + a2.y + eA;
    float accBf = b2.x + b2.y + eB;
#pragma unroll
    for (int o = 16; o; o >>= 1) {
        accAf += __shfl_xor_sync(0xffffffffu, accAf, o);
        accBf += __shfl_xor_sync(0xffffffffu, accBf, o);
    }
    if (lane == 0) {
        float rd = g_rdenom[s * NBINS + warp];
        g_ys[s * (NCH * NBINS) + c0 * NBINS + warp]       = accAf * rd;
        g_ys[s * (NCH * NBINS) + (c0 + 1) * NBINS + warp] = accBf * rd;
    }
}

// ---------------- helpers ----------------
__device__ __forceinline__ float dot4(float4 a, float4 b, float acc)
{
    acc = fmaf(a.x, b.x, acc);
    acc = fmaf(a.y, b.y, acc);
    acc = fmaf(a.z, b.z, acc);
    acc = fmaf(a.w, b.w, acc);
    return acc;
}
__device__ __forceinline__ float4 add4(float4 a, float4 b)
{ return make_float4(a.x + b.x, a.y + b.y, a.z + b.z, a.w + b.w); }

__device__ __forceinline__ float warp_red(float a)
{
#pragma unroll
    for (int o = 16; o; o >>= 1) a += __shfl_xor_sync(0xffffffffu, a, o);
    return a;
}

// ---------------- fcA: 2048x8192 GEMV, K-split 4 ----------------
// grid = 6 * 256 * 4 = 6144 blocks, 256 threads (8 rows/block).
__global__ void __launch_bounds__(256) k_fcA(const float* __restrict__ W)
{
    __shared__ float4 sx[512];                // 2048-float chunk of ys
    const int bid   = blockIdx.x;
    const int s     = bid >> 10;              // / 1024
    const int rem   = bid & 1023;
    const int chunk = rem >> 8;               // / 256
    const int row   = (rem & 255) * 8 + (threadIdx.x >> 5);
    const int lane  = threadIdx.x & 31;

    const float4* __restrict__ xv = (const float4*)(g_ys + s * 8192 + chunk * 2048);
    for (int i = threadIdx.x; i < 512; i += 256) sx[i] = xv[i];
    __syncthreads();

    const float4* __restrict__ wv =
        (const float4*)(W + (size_t)(s * 2048 + row) * 8192 + chunk * 2048);

    float a0 = 0.f, a1 = 0.f, a2 = 0.f, a3 = 0.f;
#pragma unroll 2
    for (int t = 0; t < 4; t++) {
        const int b = t * 128 + lane;
        float4 w0 = wv[b], w1 = wv[b + 32], w2 = wv[b + 64], w3 = wv[b + 96];
        a0 = dot4(w0, sx[b], a0);
        a1 = dot4(w1, sx[b + 32], a1);
        a2 = dot4(w2, sx[b + 64], a2);
        a3 = dot4(w3, sx[b + 96], a3);
    }
    float a = warp_red((a0 + a1) + (a2 + a3));
    if (lane == 0) g_h1p[chunk][s * 2048 + row] = a;
}

// ---------------- fcB: 512x2048 GEMV, K-split 2; x = sum(fcA partials)+bA ----
__global__ void __launch_bounds__(256) k_fcB(const float* __restrict__ W,
                                             const float* __restrict__ bA)
{
    __shared__ float4 sx[256];                // 1024-float chunk of h1
    const int bid   = blockIdx.x;
    const int s     = bid >> 7;               // / 128
    const int rem   = bid & 127;
    const int chunk = rem >> 6;
    const int row   = (rem & 63) * 8 + (threadIdx.x >> 5);
    const int lane  = threadIdx.x & 31;

    const int xoff = (s * 2048 + chunk * 1024) >> 2;   // float4 offset
    {
        const float4* p0 = ((const float4*)g_h1p[0]) + xoff;
        const float4* p1 = ((const float4*)g_h1p[1]) + xoff;
        const float4* p2 = ((const float4*)g_h1p[2]) + xoff;
        const float4* p3 = ((const float4*)g_h1p[3]) + xoff;
        const float4* bb = ((const float4*)bA) + xoff;
        for (int i = threadIdx.x; i < 256; i += 256)
            sx[i] = add4(add4(add4(p0[i], p1[i]), add4(p2[i], p3[i])), bb[i]);
    }
    __syncthreads();

    const float4* __restrict__ wv =
        (const float4*)(W + (size_t)(s * 512 + row) * 2048 + chunk * 1024);

    float a0 = 0.f, a1 = 0.f, a2 = 0.f, a3 = 0.f;
#pragma unroll 2
    for (int t = 0; t < 2; t++) {
        const int b = t * 128 + lane;
        float4 w0 = wv[b], w1 = wv[b + 32], w2 = wv[b + 64], w3 = wv[b + 96];
        a0 = dot4(w0, sx[b], a0);
        a1 = dot4(w1, sx[b + 32], a1);
        a2 = dot4(w2, sx[b + 64], a2);
        a3 = dot4(w3, sx[b + 96], a3);
    }
    float a = warp_red((a0 + a1) + (a2 + a3));
    if (lane == 0) g_h2p[chunk][s * 512 + row] = a;
}

// ---------------- fcC: 512x512 GEMV; x = sum(fcB partials)+bB -------------
__global__ void __launch_bounds__(256) k_fcC(const float* __restrict__ W,
                                             const float* __restrict__ bB,
                                             const float* __restrict__ bC,
                                             float* __restrict__ out)
{
    __shared__ float4 sx[128];                // 512 floats of h2
    const int bid  = blockIdx.x;
    const int s    = bid >> 6;
    const int row  = (bid & 63) * 8 + (threadIdx.x >> 5);
    const int lane = threadIdx.x & 31;

    {
        const int xoff = (s * 512) >> 2;
        const float4* p0 = ((const float4*)g_h2p[0]) + xoff;
        const float4* p1 = ((const float4*)g_h2p[1]) + xoff;
        const float4* bb = ((const float4*)bB) + xoff;
        if (threadIdx.x < 128)
            sx[threadIdx.x] = add4(add4(p0[threadIdx.x], p1[threadIdx.x]), bb[threadIdx.x]);
    }
    __syncthreads();

    const float4* __restrict__ wv = (const float4*)(W + (size_t)(s * 512 + row) * 512);

    const int b = lane;
    float a0 = dot4(wv[b],      sx[b],      0.f);
    float a1 = dot4(wv[b + 32], sx[b + 32], 0.f);
    float a2 = dot4(wv[b + 64], sx[b + 64], 0.f);
    float a3 = dot4(wv[b + 96], sx[b + 96], 0.f);
    float a = warp_red((a0 + a1) + (a2 + a3));
    if (lane == 0) {
        float r = a + bC[s * 512 + row];
        g_w0[s * 512 + row] = r;
        out[s * 960 + row]  = r;
    }
}

// ---------------- tail: p1 -> p2 -> p3 fused, 6 blocks x 1024 thr ---------
__device__ __forceinline__ void tail_layer(const float* __restrict__ W,
                                           const float* __restrict__ bias,
                                           const float* __restrict__ xsm,
                                           float* __restrict__ ysm,
                                           float* __restrict__ out, int rows, int klen,
                                           int wid, int lane)
{
    const int k4 = klen >> 2;
    for (int row = wid; row < rows; row += 32) {
        const float4* wr = (const float4*)(W + (size_t)row * klen);
        const float4* xr = (const float4*)xsm;
        float a = 0.f;
        for (int i = lane; i < k4; i += 32) a = dot4(wr[i], xr[i], a);
        a = warp_red(a);
        if (lane == 0) {
            float r = a + bias[row];
            if (ysm) ysm[row] = r;
            out[row] = r;
        }
    }
}

__global__ void __launch_bounds__(1024) k_tail(
    const float* __restrict__ p1w, const float* __restrict__ p1b,
    const float* __restrict__ p2w, const float* __restrict__ p2b,
    const float* __restrict__ p3w, const float* __restrict__ p3b,
    float* __restrict__ out)
{
    const int s = blockIdx.x;
    const int wid = threadIdx.x >> 5;
    const int lane = threadIdx.x & 31;
    __shared__ float sw0[512], sw1[256], sw2[128];

    if (threadIdx.x < 512) sw0[threadIdx.x] = g_w0[s * 512 + threadIdx.x];
    __syncthreads();
    tail_layer(p1w, p1b, sw0, sw1, out + s * 960 + 512, 256, 512, wid, lane);
    __syncthreads();
    tail_layer(p2w, p2b, sw1, sw2, out + s * 960 + 768, 128, 256, wid, lane);
    __syncthreads();
    tail_layer(p3w, p3b, sw2, nullptr, out + s * 960 + 896, 64, 128, wid, lane);
}

// ---------------- launch ----------------
extern "C" void kernel_launch(void* const* d_in, const int* in_sizes, int n_in,
                              void* d_out, int out_size)
{
    const float* xs      = (const float*)d_in[0];
    const int*   parsing = (const int*)  d_in[1];
    const float* fcA_w   = (const float*)d_in[2];
    const float* fcA_b   = (const float*)d_in[3];
    const float* fcB_w   = (const float*)d_in[4];
    const float* fcB_b   = (const float*)d_in[5];
    const float* fcC_w   = (const float*)d_in[6];
    const float* fcC_b   = (const float*)d_in[7];
    const float* p1_w    = (const float*)d_in[8];
    const float* p1_b    = (const float*)d_in[9];
    const float* p2_w    = (const float*)d_in[10];
    const float* p2_b    = (const float*)d_in[11];
    const float* p3_w    = (const float*)d_in[12];
    const float* p3_b    = (const float*)d_in[13];
    float* out = (float*)d_out;

    k_prep<<<NSEG, 512>>>(parsing);                  // #0
    k_pool<<<NSEG * 256, 512>>>(xs);                 // #1
    k_fcA <<<NSEG * 256 * 4, 256>>>(fcA_w);          // #2
    k_fcB <<<NSEG * 64 * 2, 256>>>(fcB_w, fcA_b);    // #3  <- profiled
    k_fcC <<<NSEG * 64, 256>>>(fcC_w, fcB_b, fcC_b, out);
    k_tail<<<NSEG, 1024>>>(p1_w, p1_b, p2_w, p2_b, p3_w, p3_b, out);
}